// round 4
// baseline (speedup 1.0000x reference)
#include <cuda_runtime.h>
#include <cuda_bf16.h>
#include <math.h>
#include <stdint.h>

#define TT 16
#define NN 20000
#define EE 320000
#define CC 128
#define HH 128
#define PP 100000
#define H3 384

#define ROWPAD 136            // bf16 per smem row (272 B = 17 x 16B: odd -> conflict-free ldmatrix)

// ---------------- scratch (device globals; no allocation allowed) ----------------
__device__ float g_bufA[(size_t)TT * NN * HH];
__device__ float g_bufB[(size_t)TT * NN * HH];
__device__ float g_gi[(size_t)TT * NN * H3];
__device__ float g_hst[(size_t)NN * HH];
__device__ float g_dinv[TT * NN];
__device__ int   g_cnt[TT * NN];
__device__ int   g_rowptr[TT * (NN + 1)];
__device__ int   g_cursor[TT * NN];
__device__ int   g_csrsrc[TT * EE];
// split weights (bf16 hi/lo): [0,16384) W1^T, [16384,32768) W2^T, [32768,49152) W3^T,
// [49152,98304) w_ih, [98304,147456) w_hh   (all stored [n][k], k contiguous, K=128)
__device__ __nv_bfloat16 g_wh[147456];
__device__ __nv_bfloat16 g_wl[147456];

// ---------------- PTX helpers ----------------
__device__ __forceinline__ uint32_t smem_u32(const void* p) {
    uint32_t a;
    asm("{ .reg .u64 t; cvta.to.shared.u64 t, %1; cvt.u32.u64 %0, t; }" : "=r"(a) : "l"(p));
    return a;
}
__device__ __forceinline__ void ldsm_x4(uint32_t* r, uint32_t addr) {
    asm volatile("ldmatrix.sync.aligned.m8n8.x4.shared.b16 {%0,%1,%2,%3}, [%4];"
                 : "=r"(r[0]), "=r"(r[1]), "=r"(r[2]), "=r"(r[3]) : "r"(addr));
}
__device__ __forceinline__ void mma16816(float* d, const uint32_t* a, const uint32_t* b) {
    asm volatile(
        "mma.sync.aligned.m16n8k16.row.col.f32.bf16.bf16.f32 "
        "{%0,%1,%2,%3}, {%4,%5,%6,%7}, {%8,%9}, {%0,%1,%2,%3};"
        : "+f"(d[0]), "+f"(d[1]), "+f"(d[2]), "+f"(d[3])
        : "r"(a[0]), "r"(a[1]), "r"(a[2]), "r"(a[3]), "r"(b[0]), "r"(b[1]));
}
__device__ __forceinline__ uint32_t pack_bf2(__nv_bfloat16 a, __nv_bfloat16 b) {
    uint32_t r;
    asm("mov.b32 %0, {%1, %2};" : "=r"(r) : "h"(*(uint16_t*)&a), "h"(*(uint16_t*)&b));
    return r;
}

// ---------------- small utility kernels ----------------
__global__ void zero_kernel() {
    int idx = blockIdx.x * blockDim.x + threadIdx.x;
    if (idx < TT * NN) g_cnt[idx] = 0;
    if (idx < NN * HH) g_hst[idx] = 0.f;
}

__global__ void deg_kernel(const int* __restrict__ ei) {
    int idx = blockIdx.x * blockDim.x + threadIdx.x;
    if (idx >= TT * EE) return;
    int t = idx / EE, e = idx - t * EE;
    int dst = ei[(size_t)t * 2 * EE + EE + e];
    atomicAdd(&g_cnt[t * NN + dst], 1);
}

__global__ void dinv_kernel() {
    int idx = blockIdx.x * blockDim.x + threadIdx.x;
    if (idx >= TT * NN) return;
    g_dinv[idx] = rsqrtf((float)g_cnt[idx] + 1.0f);
}

__global__ void scan_kernel() {
    const int CH = 79;
    int t = blockIdx.x;
    int tx = threadIdx.x;
    int base = t * NN;
    int st = tx * CH, en = min(st + CH, NN);
    int s = 0;
    for (int i = st; i < en; i++) s += g_cnt[base + i];
    __shared__ int sh[256];
    sh[tx] = s;
    __syncthreads();
    for (int off = 1; off < 256; off <<= 1) {
        int v = (tx >= off) ? sh[tx - off] : 0;
        __syncthreads();
        sh[tx] += v;
        __syncthreads();
    }
    int run = sh[tx] - s;
    int roff = t * (NN + 1);
    for (int i = st; i < en; i++) {
        int c = g_cnt[base + i];
        g_rowptr[roff + i] = run;
        g_cursor[base + i] = run;
        run += c;
    }
    if (tx == 255) g_rowptr[roff + NN] = sh[255];
}

__global__ void fill_kernel(const int* __restrict__ ei) {
    int idx = blockIdx.x * blockDim.x + threadIdx.x;
    if (idx >= TT * EE) return;
    int t = idx / EE, e = idx - t * EE;
    int src = ei[(size_t)t * 2 * EE + e];
    int dst = ei[(size_t)t * 2 * EE + EE + e];
    int pos = atomicAdd(&g_cursor[t * NN + dst], 1);
    g_csrsrc[(size_t)t * EE + pos] = src;
}

// split weights into bf16 hi/lo pairs, storing [n][k] (k contiguous)
__global__ void split_weights(const float* __restrict__ W1, const float* __restrict__ W2,
                              const float* __restrict__ W3, const float* __restrict__ wih,
                              const float* __restrict__ whh) {
    int idx = blockIdx.x * blockDim.x + threadIdx.x;
    if (idx >= 147456) return;
    float x;
    if (idx < 49152) {
        int w = idx / 16384, r = idx - w * 16384;
        int n = r >> 7, k = r & 127;
        const float* W = (w == 0) ? W1 : ((w == 1) ? W2 : W3);
        x = W[k * 128 + n];              // transpose: W is [K][N]
    } else {
        int j = idx - 49152;
        const float* W = (j < 49152) ? wih : whh;
        int r = (j < 49152) ? j : j - 49152;
        x = W[r];                        // already [n][k]
    }
    __nv_bfloat16 h = __float2bfloat16(x);
    g_wh[idx] = h;
    g_wl[idx] = __float2bfloat16(x - __bfloat162float(h));
}

// ---------------- split-bf16 HMMA GEMM: C[M,Ntot] = A[M,128] @ B^T (+bias, *dscale) ----------------
// grid: (ceil(M/128), Ntot/128), block 256 (8 warps: 4 in M x 2 in N).
// 3 terms: Ah*Bh + Al*Bh + Ah*Bl. Bh/Bl are bf16 [Ntot][128].
#define SMEM_MMA (4 * 128 * ROWPAD * 2)
__global__ void __launch_bounds__(256) mma_gemm(
    const float* __restrict__ A, const __nv_bfloat16* __restrict__ Bh,
    const __nv_bfloat16* __restrict__ Bl, float* __restrict__ C,
    int M, int Ntot, const float* __restrict__ bias, const float* __restrict__ dscale)
{
    extern __shared__ __nv_bfloat16 sm[];
    __nv_bfloat16* Ah = sm;                       // [128][ROWPAD]
    __nv_bfloat16* Al = sm + 128 * ROWPAD;
    __nv_bfloat16* Bsh = sm + 2 * 128 * ROWPAD;   // hi
    __nv_bfloat16* Bsl = sm + 3 * 128 * ROWPAD;   // lo

    const int tid = threadIdx.x;
    const int warp = tid >> 5, lane = tid & 31;
    const int wm = warp >> 1, wn = warp & 1;
    const int row0 = blockIdx.x * 128, col0 = blockIdx.y * 128;

    // ---- load + split A: 128 rows x 128 f32 ----
#pragma unroll
    for (int i = 0; i < 16; i++) {
        int fi = tid + i * 256;           // float4 index 0..4095
        int r = fi >> 5;                  // 0..127
        int kc = (fi & 31) * 4;           // 0..124
        float4 v = make_float4(0.f, 0.f, 0.f, 0.f);
        int gr = row0 + r;
        if (gr < M) v = *(const float4*)(A + (size_t)gr * 128 + kc);
        __nv_bfloat16 hx = __float2bfloat16(v.x), hy = __float2bfloat16(v.y);
        __nv_bfloat16 hz = __float2bfloat16(v.z), hw = __float2bfloat16(v.w);
        __nv_bfloat16 lx = __float2bfloat16(v.x - __bfloat162float(hx));
        __nv_bfloat16 ly = __float2bfloat16(v.y - __bfloat162float(hy));
        __nv_bfloat16 lz = __float2bfloat16(v.z - __bfloat162float(hz));
        __nv_bfloat16 lw = __float2bfloat16(v.w - __bfloat162float(hw));
        *(uint2*)(Ah + r * ROWPAD + kc) = make_uint2(pack_bf2(hx, hy), pack_bf2(hz, hw));
        *(uint2*)(Al + r * ROWPAD + kc) = make_uint2(pack_bf2(lx, ly), pack_bf2(lz, lw));
    }
    // ---- load B hi/lo: 128 rows x 128 bf16 each ----
#pragma unroll
    for (int i = 0; i < 16; i++) {
        int fi = tid + i * 256;           // uint4 index 0..4095
        int m = fi >> 11;                 // 0=hi, 1=lo
        int j = fi & 2047;
        int r = j >> 4;                   // 0..127
        int kc = (j & 15) * 8;            // 0..120
        const __nv_bfloat16* src = m ? Bl : Bh;
        uint4 v = *(const uint4*)(src + (size_t)(col0 + r) * 128 + kc);
        __nv_bfloat16* dst = m ? Bsl : Bsh;
        *(uint4*)(dst + r * ROWPAD + kc) = v;
    }
    __syncthreads();

    const uint32_t sbase = smem_u32(sm);
    float acc[2][8][4];
#pragma unroll
    for (int mt = 0; mt < 2; mt++)
#pragma unroll
        for (int nt = 0; nt < 8; nt++)
#pragma unroll
            for (int q = 0; q < 4; q++) acc[mt][nt][q] = 0.f;

    const uint32_t a_lane = (uint32_t)((wm * 32 + (lane & 15)) * ROWPAD + (lane >> 4) * 8) * 2;
    const uint32_t b_lane = (uint32_t)((wn * 64 + (lane & 7) + ((lane >> 4) << 3)) * ROWPAD
                                       + ((lane >> 3) & 1) * 8) * 2;

#pragma unroll
    for (int term = 0; term < 3; term++) {
        const uint32_t abase = sbase + ((term == 1) ? (128 * ROWPAD * 2) : 0) + a_lane;
        const uint32_t bbase = sbase + ((term == 2) ? (3 * 128 * ROWPAD * 2) : (2 * 128 * ROWPAD * 2)) + b_lane;
#pragma unroll
        for (int kc = 0; kc < 8; kc++) {
            uint32_t af[2][4], bf[4][4];
#pragma unroll
            for (int mt = 0; mt < 2; mt++)
                ldsm_x4(af[mt], abase + (uint32_t)(mt * 16 * ROWPAD + kc * 16) * 2);
#pragma unroll
            for (int n2 = 0; n2 < 4; n2++)
                ldsm_x4(bf[n2], bbase + (uint32_t)(n2 * 16 * ROWPAD + kc * 16) * 2);
#pragma unroll
            for (int mt = 0; mt < 2; mt++)
#pragma unroll
                for (int nt = 0; nt < 8; nt++)
                    mma16816(acc[mt][nt], af[mt], &bf[nt >> 1][(nt & 1) * 2]);
        }
    }

    // ---- epilogue ----
#pragma unroll
    for (int mt = 0; mt < 2; mt++) {
        int r_lo = row0 + wm * 32 + mt * 16 + (lane >> 2);
        int r_hi = r_lo + 8;
        float ds_lo = 1.f, ds_hi = 1.f;
        if (dscale) {
            if (r_lo < M) ds_lo = dscale[r_lo];
            if (r_hi < M) ds_hi = dscale[r_hi];
        }
#pragma unroll
        for (int nt = 0; nt < 8; nt++) {
            int gc = col0 + wn * 64 + nt * 8 + (lane & 3) * 2;
            float bx = 0.f, by = 0.f;
            if (bias) { bx = bias[gc]; by = bias[gc + 1]; }
            if (r_lo < M)
                *(float2*)(C + (size_t)r_lo * Ntot + gc) =
                    make_float2(acc[mt][nt][0] * ds_lo + bx, acc[mt][nt][1] * ds_lo + by);
            if (r_hi < M)
                *(float2*)(C + (size_t)r_hi * Ntot + gc) =
                    make_float2(acc[mt][nt][2] * ds_hi + bx, acc[mt][nt][3] * ds_hi + by);
        }
    }
}

// ---------------- GCN aggregation: warp-per-node float4 gather on pre-scaled h' ----------------
// hp holds h' = dinv[row] * (X W). out = dinv[i]*(sum_s h'[s] + h'[i]) + bias  (then relu)
__global__ void __launch_bounds__(256) gather_kernel(
    const float* __restrict__ hp, float* __restrict__ outp,
    const float* __restrict__ bias, int relu)
{
    int t = blockIdx.y;
    int warp = threadIdx.x >> 5, lane = threadIdx.x & 31;
    int i = blockIdx.x * 8 + warp;
    if (i >= NN) return;
    int roff = t * (NN + 1);
    int ks = g_rowptr[roff + i];
    int ke = g_rowptr[roff + i + 1];
    const int* __restrict__ srcs = g_csrsrc + (size_t)t * EE;
    const float* __restrict__ hf = hp + (size_t)t * NN * HH;
    int c = lane * 4;
    float4 acc = make_float4(0.f, 0.f, 0.f, 0.f);
    int k = ks;
    for (; k + 1 < ke; k += 2) {
        int s0 = __ldg(srcs + k);
        int s1 = __ldg(srcs + k + 1);
        float4 v0 = *(const float4*)(hf + (size_t)s0 * HH + c);
        float4 v1 = *(const float4*)(hf + (size_t)s1 * HH + c);
        acc.x += v0.x + v1.x; acc.y += v0.y + v1.y;
        acc.z += v0.z + v1.z; acc.w += v0.w + v1.w;
    }
    if (k < ke) {
        int s = __ldg(srcs + k);
        float4 v = *(const float4*)(hf + (size_t)s * HH + c);
        acc.x += v.x; acc.y += v.y; acc.z += v.z; acc.w += v.w;
    }
    float di = g_dinv[t * NN + i];
    float4 hi = *(const float4*)(hf + (size_t)i * HH + c);
    float4 bv = *(const float4*)(bias + c);
    float4 o;
    o.x = di * (acc.x + hi.x) + bv.x;
    o.y = di * (acc.y + hi.y) + bv.y;
    o.z = di * (acc.z + hi.z) + bv.z;
    o.w = di * (acc.w + hi.w) + bv.w;
    if (relu) {
        o.x = fmaxf(o.x, 0.f); o.y = fmaxf(o.y, 0.f);
        o.z = fmaxf(o.z, 0.f); o.w = fmaxf(o.w, 0.f);
    }
    *(float4*)(outp + (size_t)t * NN * HH + (size_t)i * HH + c) = o;
}

// ---------------- fused GRU step: gh = hst @ w_hh^T (split-bf16 HMMA) + gate elementwise ----------------
// grid: ceil(NN/64) blocks, 256 threads (8 warps: 2 M-groups x 4 N-groups; warp tile 32x96).
#define GM 64
#define BSTR 24
#define GRU_STAGE (GM * 385)                       // f32 staging 64 x 384 (+pad)
#define SMEM_GRU (GRU_STAGE * 4 + H3 * BSTR * 2)
__global__ void __launch_bounds__(256) gru_step(
    const __nv_bfloat16* __restrict__ Bh, const __nv_bfloat16* __restrict__ Bl,
    const float* __restrict__ b_hh, int t)
{
    extern __shared__ float smf[];
    float* stage = smf;                            // reuses A region after mainloop
    __nv_bfloat16* Ah = (__nv_bfloat16*)smf;       // [GM][ROWPAD]
    __nv_bfloat16* Al = Ah + GM * ROWPAD;
    __nv_bfloat16* Bc = (__nv_bfloat16*)(smf + GRU_STAGE);  // [384][BSTR] chunk

    const int tid = threadIdx.x, warp = tid >> 5, lane = tid & 31;
    const int wm = warp >> 2, wn = warp & 3;       // 2 x 4
    const int m0 = blockIdx.x * GM;

    // load + split A = hst[m0..m0+64) x 128
#pragma unroll
    for (int i = 0; i < 8; i++) {
        int fi = tid + i * 256;      // 0..2047 float4
        int r = fi >> 5, kc = (fi & 31) * 4;
        int gr = m0 + r;
        float4 v = make_float4(0.f, 0.f, 0.f, 0.f);
        if (gr < NN) v = *(const float4*)(g_hst + (size_t)gr * HH + kc);
        __nv_bfloat16 hx = __float2bfloat16(v.x), hy = __float2bfloat16(v.y);
        __nv_bfloat16 hz = __float2bfloat16(v.z), hw = __float2bfloat16(v.w);
        __nv_bfloat16 lx = __float2bfloat16(v.x - __bfloat162float(hx));
        __nv_bfloat16 ly = __float2bfloat16(v.y - __bfloat162float(hy));
        __nv_bfloat16 lz = __float2bfloat16(v.z - __bfloat162float(hz));
        __nv_bfloat16 lw = __float2bfloat16(v.w - __bfloat162float(hw));
        *(uint2*)(Ah + r * ROWPAD + kc) = make_uint2(pack_bf2(hx, hy), pack_bf2(hz, hw));
        *(uint2*)(Al + r * ROWPAD + kc) = make_uint2(pack_bf2(lx, ly), pack_bf2(lz, lw));
    }

    float acc[24][4];                              // mt(2) x nt(12)
#pragma unroll
    for (int q = 0; q < 24; q++) {
        acc[q][0] = 0.f; acc[q][1] = 0.f; acc[q][2] = 0.f; acc[q][3] = 0.f;
    }

    const uint32_t sbase = smem_u32(smf);
    const uint32_t bcbase = smem_u32(Bc);
    const uint32_t a_lane = (uint32_t)((wm * 32 + (lane & 15)) * ROWPAD + (lane >> 4) * 8) * 2;
    const uint32_t b_lane = (uint32_t)((wn * 96 + (lane & 7) + ((lane >> 4) << 3)) * BSTR
                                       + ((lane >> 3) & 1) * 8) * 2;

#pragma unroll 1
    for (int term = 0; term < 3; term++) {
        const __nv_bfloat16* Bsrc = (term == 2) ? Bl : Bh;
        const uint32_t abase = sbase + ((term == 1) ? (GM * ROWPAD * 2) : 0) + a_lane;
#pragma unroll 1
        for (int kc = 0; kc < 8; kc++) {
            __syncthreads();
            // load B chunk: 384 n-rows x 16 k (2 uint4 per row)
#pragma unroll
            for (int i = 0; i < 3; i++) {
                int u = tid + i * 256;           // 0..767
                int r = u >> 1;
                int cc = (u & 1) * 8;
                uint4 v = *(const uint4*)(Bsrc + (size_t)r * 128 + kc * 16 + cc);
                *(uint4*)(Bc + r * BSTR + cc) = v;
            }
            __syncthreads();
            uint32_t af[2][4];
#pragma unroll
            for (int mt = 0; mt < 2; mt++)
                ldsm_x4(af[mt], abase + (uint32_t)(mt * 16 * ROWPAD + kc * 16) * 2);
#pragma unroll
            for (int n2 = 0; n2 < 6; n2++) {
                uint32_t bf[4];
                ldsm_x4(bf, bcbase + b_lane + (uint32_t)(n2 * 16 * BSTR) * 2);
#pragma unroll
                for (int mt = 0; mt < 2; mt++) {
                    mma16816(acc[mt * 12 + n2 * 2 + 0], af[mt], bf);
                    mma16816(acc[mt * 12 + n2 * 2 + 1], af[mt], bf + 2);
                }
            }
        }
    }
    __syncthreads();   // A region consumed; safe to overwrite with stage

    // stage gh accs to smem [64][385]
#pragma unroll
    for (int mt = 0; mt < 2; mt++) {
        int r = wm * 32 + mt * 16 + (lane >> 2);
#pragma unroll
        for (int n2 = 0; n2 < 6; n2++) {
#pragma unroll
            for (int h = 0; h < 2; h++) {
                int nt = n2 * 2 + h;
                int cbase = wn * 96 + n2 * 16 + h * 8 + (lane & 3) * 2;
                float* a4 = acc[mt * 12 + nt];
                stage[r * 385 + cbase]       = a4[0];
                stage[r * 385 + cbase + 1]   = a4[1];
                stage[(r + 8) * 385 + cbase]     = a4[2];
                stage[(r + 8) * 385 + cbase + 1] = a4[3];
            }
        }
    }
    __syncthreads();

    // elementwise gates
    for (int e = tid; e < GM * HH; e += 256) {
        int r = e >> 7, j = e & 127;
        int row = m0 + r;
        if (row >= NN) continue;
        const float* gi = g_gi + ((size_t)t * NN + row) * H3;
        float ghr = stage[r * 385 + j]       + b_hh[j];
        float ghz = stage[r * 385 + 128 + j] + b_hh[128 + j];
        float ghn = stage[r * 385 + 256 + j] + b_hh[256 + j];
        float ir = gi[j], iz = gi[128 + j], inn = gi[256 + j];
        float hp = g_hst[(size_t)row * HH + j];
        float rr = 1.f / (1.f + expf(-(ir + ghr)));
        float zz = 1.f / (1.f + expf(-(iz + ghz)));
        float nn2 = tanhf(inn + rr * ghn);
        g_hst[(size_t)row * HH + j] = (1.f - zz) * nn2 + zz * hp;
    }
}

// ---------------- decoder ----------------
__global__ void decode_kernel(const int* __restrict__ ep, float* __restrict__ out) {
    int gid = blockIdx.x * blockDim.x + threadIdx.x;
    int w = gid >> 5, lane = gid & 31;
    if (w >= PP) return;
    int s = ep[w], d = ep[PP + w];
    float4 a = *(const float4*)&g_hst[(size_t)s * HH + lane * 4];
    float4 b = *(const float4*)&g_hst[(size_t)d * HH + lane * 4];
    float v = a.x * b.x + a.y * b.y + a.z * b.z + a.w * b.w;
#pragma unroll
    for (int off = 16; off; off >>= 1) v += __shfl_down_sync(0xffffffffu, v, off);
    if (lane == 0) out[w] = v;
}

// ---------------- launch ----------------
extern "C" void kernel_launch(void* const* d_in, const int* in_sizes, int n_in,
                              void* d_out, int out_size)
{
    const float* x_seq  = (const float*)d_in[0];
    const int* edge_index = (const int*)d_in[1];
    const int* edge_pairs = (const int*)d_in[2];
    const float* W1 = (const float*)d_in[3];
    const float* b1 = (const float*)d_in[4];
    const float* W2 = (const float*)d_in[5];
    const float* b2 = (const float*)d_in[6];
    const float* W3 = (const float*)d_in[7];
    const float* b3 = (const float*)d_in[8];
    const float* w_ih = (const float*)d_in[9];
    const float* w_hh = (const float*)d_in[10];
    const float* b_ih = (const float*)d_in[11];
    const float* b_hh = (const float*)d_in[12];
    float* out = (float*)d_out;

    float *bufA, *bufB, *gi, *dinv;
    __nv_bfloat16 *wh, *wl;
    cudaGetSymbolAddress((void**)&bufA, g_bufA);
    cudaGetSymbolAddress((void**)&bufB, g_bufB);
    cudaGetSymbolAddress((void**)&gi,   g_gi);
    cudaGetSymbolAddress((void**)&dinv, g_dinv);
    cudaGetSymbolAddress((void**)&wh,   g_wh);
    cudaGetSymbolAddress((void**)&wl,   g_wl);

    cudaFuncSetAttribute(mma_gemm, cudaFuncAttributeMaxDynamicSharedMemorySize, SMEM_MMA);
    cudaFuncSetAttribute(gru_step, cudaFuncAttributeMaxDynamicSharedMemorySize, SMEM_GRU);

    // graph prep
    zero_kernel<<<(NN * HH + 255) / 256, 256>>>();
    deg_kernel<<<(TT * EE + 255) / 256, 256>>>(edge_index);
    dinv_kernel<<<(TT * NN + 255) / 256, 256>>>();
    scan_kernel<<<TT, 256>>>();
    fill_kernel<<<(TT * EE + 255) / 256, 256>>>(edge_index);
    split_weights<<<(147456 + 255) / 256, 256>>>(W1, W2, W3, w_ih, w_hh);

    const int MB = (TT * NN + 127) / 128;   // 2500
    dim3 gGather(NN / 8, TT);               // warp-per-node, 8 nodes/block

    // GCN stack; GEMM epilogue pre-scales by dinv (h' = dinv * XW)
    mma_gemm<<<dim3(MB, 1), 256, SMEM_MMA>>>(x_seq, wh,        wl,        bufA, TT * NN, HH, nullptr, dinv);
    gather_kernel<<<gGather, 256>>>(bufA, bufB, b1, 1);
    mma_gemm<<<dim3(MB, 1), 256, SMEM_MMA>>>(bufB, wh + 16384, wl + 16384, bufA, TT * NN, HH, nullptr, dinv);
    gather_kernel<<<gGather, 256>>>(bufA, bufB, b2, 1);
    mma_gemm<<<dim3(MB, 1), 256, SMEM_MMA>>>(bufB, wh + 32768, wl + 32768, bufA, TT * NN, HH, nullptr, dinv);
    gather_kernel<<<gGather, 256>>>(bufA, bufB, b3, 0);
    // feats in bufB

    // GRU input projections (one big GEMM over all frames)
    mma_gemm<<<dim3(MB, 3), 256, SMEM_MMA>>>(bufB, wh + 49152, wl + 49152, gi, TT * NN, H3, b_ih, nullptr);

    // fused GRU steps
    const int GB = (NN + GM - 1) / GM;      // 313
    for (int t = 0; t < TT; t++)
        gru_step<<<GB, 256, SMEM_GRU>>>(wh + 98304, wl + 98304, b_hh, t);

    decode_kernel<<<(PP * 32 + 255) / 256, 256>>>(edge_pairs, out);
}

// round 5
// speedup vs baseline: 1.5891x; 1.5891x over previous
#include <cuda_runtime.h>
#include <cuda_bf16.h>
#include <math.h>
#include <stdint.h>

#define TT 16
#define NN 20000
#define EE 320000
#define CC 128
#define HH 128
#define PP 100000
#define H3 384

#define ROWPAD 136            // bf16 per smem row (272 B = 17 x 16B: odd -> conflict-free ldmatrix)

// ---------------- scratch (device globals; no allocation allowed) ----------------
__device__ float g_bufA[(size_t)TT * NN * HH];
__device__ float g_bufB[(size_t)TT * NN * HH];
__device__ float g_gi[(size_t)TT * NN * H3];
__device__ float g_gh[(size_t)NN * H3];
__device__ float g_hst[(size_t)NN * HH];
__device__ float g_dinv[TT * NN];
__device__ int   g_cnt[TT * NN];
__device__ int   g_rowptr[TT * (NN + 1)];
__device__ int   g_cursor[TT * NN];
__device__ int   g_csrsrc[TT * EE];
// split weights (bf16 hi/lo): [0,16384) W1^T, [16384,32768) W2^T, [32768,49152) W3^T,
// [49152,98304) w_ih, [98304,147456) w_hh   (all stored [n][k], k contiguous, K=128)
__device__ __nv_bfloat16 g_wh[147456];
__device__ __nv_bfloat16 g_wl[147456];

// ---------------- PTX helpers ----------------
__device__ __forceinline__ uint32_t smem_u32(const void* p) {
    uint32_t a;
    asm("{ .reg .u64 t; cvta.to.shared.u64 t, %1; cvt.u32.u64 %0, t; }" : "=r"(a) : "l"(p));
    return a;
}
__device__ __forceinline__ void ldsm_x4(uint32_t* r, uint32_t addr) {
    asm volatile("ldmatrix.sync.aligned.m8n8.x4.shared.b16 {%0,%1,%2,%3}, [%4];"
                 : "=r"(r[0]), "=r"(r[1]), "=r"(r[2]), "=r"(r[3]) : "r"(addr));
}
__device__ __forceinline__ void mma16816(float* d, const uint32_t* a, const uint32_t* b) {
    asm volatile(
        "mma.sync.aligned.m16n8k16.row.col.f32.bf16.bf16.f32 "
        "{%0,%1,%2,%3}, {%4,%5,%6,%7}, {%8,%9}, {%0,%1,%2,%3};"
        : "+f"(d[0]), "+f"(d[1]), "+f"(d[2]), "+f"(d[3])
        : "r"(a[0]), "r"(a[1]), "r"(a[2]), "r"(a[3]), "r"(b[0]), "r"(b[1]));
}
__device__ __forceinline__ uint32_t pack_bf2(__nv_bfloat16 a, __nv_bfloat16 b) {
    uint32_t r;
    asm("mov.b32 %0, {%1, %2};" : "=r"(r) : "h"(*(uint16_t*)&a), "h"(*(uint16_t*)&b));
    return r;
}

// ---------------- small utility kernels ----------------
__global__ void zero_kernel() {
    int idx = blockIdx.x * blockDim.x + threadIdx.x;
    if (idx < TT * NN) g_cnt[idx] = 0;
    if (idx < NN * HH) g_hst[idx] = 0.f;
}

__global__ void deg_kernel(const int* __restrict__ ei) {
    int idx = blockIdx.x * blockDim.x + threadIdx.x;
    if (idx >= TT * EE) return;
    int t = idx / EE, e = idx - t * EE;
    int dst = ei[(size_t)t * 2 * EE + EE + e];
    atomicAdd(&g_cnt[t * NN + dst], 1);
}

__global__ void dinv_kernel() {
    int idx = blockIdx.x * blockDim.x + threadIdx.x;
    if (idx >= TT * NN) return;
    g_dinv[idx] = rsqrtf((float)g_cnt[idx] + 1.0f);
}

__global__ void scan_kernel() {
    const int CH = 79;
    int t = blockIdx.x;
    int tx = threadIdx.x;
    int base = t * NN;
    int st = tx * CH, en = min(st + CH, NN);
    int s = 0;
    for (int i = st; i < en; i++) s += g_cnt[base + i];
    __shared__ int sh[256];
    sh[tx] = s;
    __syncthreads();
    for (int off = 1; off < 256; off <<= 1) {
        int v = (tx >= off) ? sh[tx - off] : 0;
        __syncthreads();
        sh[tx] += v;
        __syncthreads();
    }
    int run = sh[tx] - s;
    int roff = t * (NN + 1);
    for (int i = st; i < en; i++) {
        int c = g_cnt[base + i];
        g_rowptr[roff + i] = run;
        g_cursor[base + i] = run;
        run += c;
    }
    if (tx == 255) g_rowptr[roff + NN] = sh[255];
}

__global__ void fill_kernel(const int* __restrict__ ei) {
    int idx = blockIdx.x * blockDim.x + threadIdx.x;
    if (idx >= TT * EE) return;
    int t = idx / EE, e = idx - t * EE;
    int src = ei[(size_t)t * 2 * EE + e];
    int dst = ei[(size_t)t * 2 * EE + EE + e];
    int pos = atomicAdd(&g_cursor[t * NN + dst], 1);
    g_csrsrc[(size_t)t * EE + pos] = src;
}

// split weights into bf16 hi/lo pairs, storing [n][k] (k contiguous)
__global__ void split_weights(const float* __restrict__ W1, const float* __restrict__ W2,
                              const float* __restrict__ W3, const float* __restrict__ wih,
                              const float* __restrict__ whh) {
    int idx = blockIdx.x * blockDim.x + threadIdx.x;
    if (idx >= 147456) return;
    float x;
    if (idx < 49152) {
        int w = idx / 16384, r = idx - w * 16384;
        int n = r >> 7, k = r & 127;
        const float* W = (w == 0) ? W1 : ((w == 1) ? W2 : W3);
        x = W[k * 128 + n];              // transpose: W is [K][N]
    } else {
        int j = idx - 49152;
        const float* W = (j < 49152) ? wih : whh;
        int r = (j < 49152) ? j : j - 49152;
        x = W[r];                        // already [n][k]
    }
    __nv_bfloat16 h = __float2bfloat16(x);
    g_wh[idx] = h;
    g_wl[idx] = __float2bfloat16(x - __bfloat162float(h));
}

// ---------------- split-bf16 HMMA GEMM: C[M,Ntot] = A[M,128] @ B^T (+bias, *dscale) ----------------
// grid: (ceil(M/128), Ntot/128), block 256 (8 warps: 4 in M x 2 in N).
// 3 terms: Ah*Bh + Al*Bh + Ah*Bl. Bh/Bl are bf16 [Ntot][128].
#define SMEM_MMA (4 * 128 * ROWPAD * 2)
__global__ void __launch_bounds__(256) mma_gemm(
    const float* __restrict__ A, const __nv_bfloat16* __restrict__ Bh,
    const __nv_bfloat16* __restrict__ Bl, float* __restrict__ C,
    int M, int Ntot, const float* __restrict__ bias, const float* __restrict__ dscale)
{
    extern __shared__ __nv_bfloat16 sm[];
    __nv_bfloat16* Ah = sm;                       // [128][ROWPAD]
    __nv_bfloat16* Al = sm + 128 * ROWPAD;
    __nv_bfloat16* Bsh = sm + 2 * 128 * ROWPAD;   // hi
    __nv_bfloat16* Bsl = sm + 3 * 128 * ROWPAD;   // lo

    const int tid = threadIdx.x;
    const int warp = tid >> 5, lane = tid & 31;
    const int wm = warp >> 1, wn = warp & 1;
    const int row0 = blockIdx.x * 128, col0 = blockIdx.y * 128;

    // ---- load + split A: 128 rows x 128 f32 ----
#pragma unroll
    for (int i = 0; i < 16; i++) {
        int fi = tid + i * 256;           // float4 index 0..4095
        int r = fi >> 5;                  // 0..127
        int kc = (fi & 31) * 4;           // 0..124
        float4 v = make_float4(0.f, 0.f, 0.f, 0.f);
        int gr = row0 + r;
        if (gr < M) v = *(const float4*)(A + (size_t)gr * 128 + kc);
        __nv_bfloat16 hx = __float2bfloat16(v.x), hy = __float2bfloat16(v.y);
        __nv_bfloat16 hz = __float2bfloat16(v.z), hw = __float2bfloat16(v.w);
        __nv_bfloat16 lx = __float2bfloat16(v.x - __bfloat162float(hx));
        __nv_bfloat16 ly = __float2bfloat16(v.y - __bfloat162float(hy));
        __nv_bfloat16 lz = __float2bfloat16(v.z - __bfloat162float(hz));
        __nv_bfloat16 lw = __float2bfloat16(v.w - __bfloat162float(hw));
        *(uint2*)(Ah + r * ROWPAD + kc) = make_uint2(pack_bf2(hx, hy), pack_bf2(hz, hw));
        *(uint2*)(Al + r * ROWPAD + kc) = make_uint2(pack_bf2(lx, ly), pack_bf2(lz, lw));
    }
    // ---- load B hi/lo: 128 rows x 128 bf16 each ----
#pragma unroll
    for (int i = 0; i < 16; i++) {
        int fi = tid + i * 256;           // uint4 index 0..4095
        int m = fi >> 11;                 // 0=hi, 1=lo
        int j = fi & 2047;
        int r = j >> 4;                   // 0..127
        int kc = (j & 15) * 8;            // 0..120
        const __nv_bfloat16* src = m ? Bl : Bh;
        uint4 v = *(const uint4*)(src + (size_t)(col0 + r) * 128 + kc);
        __nv_bfloat16* dst = m ? Bsl : Bsh;
        *(uint4*)(dst + r * ROWPAD + kc) = v;
    }
    __syncthreads();

    const uint32_t sbase = smem_u32(sm);
    float acc[2][8][4];
#pragma unroll
    for (int mt = 0; mt < 2; mt++)
#pragma unroll
        for (int nt = 0; nt < 8; nt++)
#pragma unroll
            for (int q = 0; q < 4; q++) acc[mt][nt][q] = 0.f;

    const uint32_t a_lane = (uint32_t)((wm * 32 + (lane & 15)) * ROWPAD + (lane >> 4) * 8) * 2;
    const uint32_t b_lane = (uint32_t)((wn * 64 + (lane & 7) + ((lane >> 4) << 3)) * ROWPAD
                                       + ((lane >> 3) & 1) * 8) * 2;

#pragma unroll
    for (int term = 0; term < 3; term++) {
        const uint32_t abase = sbase + ((term == 1) ? (128 * ROWPAD * 2) : 0) + a_lane;
        const uint32_t bbase = sbase + ((term == 2) ? (3 * 128 * ROWPAD * 2) : (2 * 128 * ROWPAD * 2)) + b_lane;
#pragma unroll
        for (int kc = 0; kc < 8; kc++) {
            uint32_t af[2][4], bf[4][4];
#pragma unroll
            for (int mt = 0; mt < 2; mt++)
                ldsm_x4(af[mt], abase + (uint32_t)(mt * 16 * ROWPAD + kc * 16) * 2);
#pragma unroll
            for (int n2 = 0; n2 < 4; n2++)
                ldsm_x4(bf[n2], bbase + (uint32_t)(n2 * 16 * ROWPAD + kc * 16) * 2);
#pragma unroll
            for (int mt = 0; mt < 2; mt++)
#pragma unroll
                for (int nt = 0; nt < 8; nt++)
                    mma16816(acc[mt][nt], af[mt], &bf[nt >> 1][(nt & 1) * 2]);
        }
    }

    // ---- epilogue ----
#pragma unroll
    for (int mt = 0; mt < 2; mt++) {
        int r_lo = row0 + wm * 32 + mt * 16 + (lane >> 2);
        int r_hi = r_lo + 8;
        float ds_lo = 1.f, ds_hi = 1.f;
        if (dscale) {
            if (r_lo < M) ds_lo = dscale[r_lo];
            if (r_hi < M) ds_hi = dscale[r_hi];
        }
#pragma unroll
        for (int nt = 0; nt < 8; nt++) {
            int gc = col0 + wn * 64 + nt * 8 + (lane & 3) * 2;
            float bx = 0.f, by = 0.f;
            if (bias) { bx = bias[gc]; by = bias[gc + 1]; }
            if (r_lo < M)
                *(float2*)(C + (size_t)r_lo * Ntot + gc) =
                    make_float2(acc[mt][nt][0] * ds_lo + bx, acc[mt][nt][1] * ds_lo + by);
            if (r_hi < M)
                *(float2*)(C + (size_t)r_hi * Ntot + gc) =
                    make_float2(acc[mt][nt][2] * ds_hi + bx, acc[mt][nt][3] * ds_hi + by);
        }
    }
}

// ---------------- GCN aggregation: warp-per-node float4 gather on pre-scaled h' ----------------
// hp holds h' = dinv[row] * (X W). out = dinv[i]*(sum_s h'[s] + h'[i]) + bias  (then relu)
__global__ void __launch_bounds__(256) gather_kernel(
    const float* __restrict__ hp, float* __restrict__ outp,
    const float* __restrict__ bias, int relu)
{
    int t = blockIdx.y;
    int warp = threadIdx.x >> 5, lane = threadIdx.x & 31;
    int i = blockIdx.x * 8 + warp;
    if (i >= NN) return;
    int roff = t * (NN + 1);
    int ks = g_rowptr[roff + i];
    int ke = g_rowptr[roff + i + 1];
    const int* __restrict__ srcs = g_csrsrc + (size_t)t * EE;
    const float* __restrict__ hf = hp + (size_t)t * NN * HH;
    int c = lane * 4;
    float4 acc = make_float4(0.f, 0.f, 0.f, 0.f);
    int k = ks;
    for (; k + 1 < ke; k += 2) {
        int s0 = __ldg(srcs + k);
        int s1 = __ldg(srcs + k + 1);
        float4 v0 = *(const float4*)(hf + (size_t)s0 * HH + c);
        float4 v1 = *(const float4*)(hf + (size_t)s1 * HH + c);
        acc.x += v0.x + v1.x; acc.y += v0.y + v1.y;
        acc.z += v0.z + v1.z; acc.w += v0.w + v1.w;
    }
    if (k < ke) {
        int s = __ldg(srcs + k);
        float4 v = *(const float4*)(hf + (size_t)s * HH + c);
        acc.x += v.x; acc.y += v.y; acc.z += v.z; acc.w += v.w;
    }
    float di = g_dinv[t * NN + i];
    float4 hi = *(const float4*)(hf + (size_t)i * HH + c);
    float4 bv = *(const float4*)(bias + c);
    float4 o;
    o.x = di * (acc.x + hi.x) + bv.x;
    o.y = di * (acc.y + hi.y) + bv.y;
    o.z = di * (acc.z + hi.z) + bv.z;
    o.w = di * (acc.w + hi.w) + bv.w;
    if (relu) {
        o.x = fmaxf(o.x, 0.f); o.y = fmaxf(o.y, 0.f);
        o.z = fmaxf(o.z, 0.f); o.w = fmaxf(o.w, 0.f);
    }
    *(float4*)(outp + (size_t)t * NN * HH + (size_t)i * HH + c) = o;
}

// ---------------- GRU elementwise step ----------------
__global__ void gru_elem(int t) {
    int idx = blockIdx.x * blockDim.x + threadIdx.x;
    if (idx >= NN * HH) return;
    int n = idx >> 7, j = idx & 127;
    const float* gi = g_gi + ((size_t)t * NN + n) * H3;
    const float* gh = g_gh + (size_t)n * H3;
    float ir = gi[j], iz = gi[HH + j], in_ = gi[2 * HH + j];
    float hr = gh[j], hz = gh[HH + j], hn = gh[2 * HH + j];
    float hp = g_hst[idx];
    float r = 1.f / (1.f + expf(-(ir + hr)));
    float z = 1.f / (1.f + expf(-(iz + hz)));
    float nn = tanhf(in_ + r * hn);
    g_hst[idx] = (1.f - z) * nn + z * hp;
}

// ---------------- decoder ----------------
__global__ void decode_kernel(const int* __restrict__ ep, float* __restrict__ out) {
    int gid = blockIdx.x * blockDim.x + threadIdx.x;
    int w = gid >> 5, lane = gid & 31;
    if (w >= PP) return;
    int s = ep[w], d = ep[PP + w];
    float4 a = *(const float4*)&g_hst[(size_t)s * HH + lane * 4];
    float4 b = *(const float4*)&g_hst[(size_t)d * HH + lane * 4];
    float v = a.x * b.x + a.y * b.y + a.z * b.z + a.w * b.w;
#pragma unroll
    for (int off = 16; off; off >>= 1) v += __shfl_down_sync(0xffffffffu, v, off);
    if (lane == 0) out[w] = v;
}

// ---------------- launch ----------------
extern "C" void kernel_launch(void* const* d_in, const int* in_sizes, int n_in,
                              void* d_out, int out_size)
{
    const float* x_seq  = (const float*)d_in[0];
    const int* edge_index = (const int*)d_in[1];
    const int* edge_pairs = (const int*)d_in[2];
    const float* W1 = (const float*)d_in[3];
    const float* b1 = (const float*)d_in[4];
    const float* W2 = (const float*)d_in[5];
    const float* b2 = (const float*)d_in[6];
    const float* W3 = (const float*)d_in[7];
    const float* b3 = (const float*)d_in[8];
    const float* w_ih = (const float*)d_in[9];
    const float* w_hh = (const float*)d_in[10];
    const float* b_ih = (const float*)d_in[11];
    const float* b_hh = (const float*)d_in[12];
    float* out = (float*)d_out;

    float *bufA, *bufB, *gi, *gh, *hst, *dinv;
    __nv_bfloat16 *wh, *wl;
    cudaGetSymbolAddress((void**)&bufA, g_bufA);
    cudaGetSymbolAddress((void**)&bufB, g_bufB);
    cudaGetSymbolAddress((void**)&gi,   g_gi);
    cudaGetSymbolAddress((void**)&gh,   g_gh);
    cudaGetSymbolAddress((void**)&hst,  g_hst);
    cudaGetSymbolAddress((void**)&dinv, g_dinv);
    cudaGetSymbolAddress((void**)&wh,   g_wh);
    cudaGetSymbolAddress((void**)&wl,   g_wl);

    cudaFuncSetAttribute(mma_gemm, cudaFuncAttributeMaxDynamicSharedMemorySize, SMEM_MMA);

    // graph prep
    zero_kernel<<<(NN * HH + 255) / 256, 256>>>();
    deg_kernel<<<(TT * EE + 255) / 256, 256>>>(edge_index);
    dinv_kernel<<<(TT * NN + 255) / 256, 256>>>();
    scan_kernel<<<TT, 256>>>();
    fill_kernel<<<(TT * EE + 255) / 256, 256>>>(edge_index);
    split_weights<<<(147456 + 255) / 256, 256>>>(W1, W2, W3, w_ih, w_hh);

    const int MB = (TT * NN + 127) / 128;   // 2500
    dim3 gGather(NN / 8, TT);               // warp-per-node, 8 nodes/block

    // GCN stack; GEMM epilogue pre-scales by dinv (h' = dinv * XW)
    mma_gemm<<<dim3(MB, 1), 256, SMEM_MMA>>>(x_seq, wh,        wl,        bufA, TT * NN, HH, nullptr, dinv);
    gather_kernel<<<gGather, 256>>>(bufA, bufB, b1, 1);
    mma_gemm<<<dim3(MB, 1), 256, SMEM_MMA>>>(bufB, wh + 16384, wl + 16384, bufA, TT * NN, HH, nullptr, dinv);
    gather_kernel<<<gGather, 256>>>(bufA, bufB, b2, 1);
    mma_gemm<<<dim3(MB, 1), 256, SMEM_MMA>>>(bufB, wh + 32768, wl + 32768, bufA, TT * NN, HH, nullptr, dinv);
    gather_kernel<<<gGather, 256>>>(bufA, bufB, b3, 0);
    // feats in bufB

    // GRU input projections (one big GEMM over all frames)
    mma_gemm<<<dim3(MB, 3), 256, SMEM_MMA>>>(bufB, wh + 49152, wl + 49152, gi, TT * NN, H3, b_ih, nullptr);

    // GRU steps: gh GEMM (B resident in smem) + elementwise
    const int MBH = (NN + 127) / 128;       // 157
    for (int t = 0; t < TT; t++) {
        mma_gemm<<<dim3(MBH, 3), 256, SMEM_MMA>>>(hst, wh + 98304, wl + 98304, gh, NN, H3, b_hh, nullptr);
        gru_elem<<<(NN * HH + 255) / 256, 256>>>(t);
    }

    decode_kernel<<<(PP * 32 + 255) / 256, 256>>>(edge_pairs, out);
}